// round 2
// baseline (speedup 1.0000x reference)
#include <cuda_runtime.h>

// Per-camera folded constants, computed by a tiny setup kernel each launch.
// Layout per camera (stride 24 floats):
//  [0..8]  R row-major, [9..11] t, [12..15] k1,k2,k3,k4,
//  [16..21] A0x,A0y,A0c,A1x,A1y,A1c  (post_rots@intrins rows 0/1 with
//           post_trans and the /(wh-1)*2-1 normalization folded in)
#define NCAM 24
__device__ float g_cam[NCAM * 24];

__global__ void setup_kernel(const float* __restrict__ rots,
                             const float* __restrict__ trans,
                             const float* __restrict__ intrins,
                             const float* __restrict__ distorts,
                             const float* __restrict__ post_rots,
                             const float* __restrict__ post_trans) {
    int c = threadIdx.x;
    if (c >= NCAM) return;
    float* o = &g_cam[c * 24];
    const float* R = rots + c * 9;
#pragma unroll
    for (int i = 0; i < 9; i++) o[i] = R[i];
    o[9]  = trans[c * 3 + 0];
    o[10] = trans[c * 3 + 1];
    o[11] = trans[c * 3 + 2];
    const float* d = distorts + c * 8;
    o[12] = d[0]; o[13] = d[1]; o[14] = d[4]; o[15] = d[5];
    const float* K = intrins + c * 9;
    const float* P = post_rots + c * 9;
    float PK[2][3];
#pragma unroll
    for (int i = 0; i < 2; i++)
#pragma unroll
        for (int j = 0; j < 3; j++)
            PK[i][j] = P[i * 3 + 0] * K[0 * 3 + j]
                     + P[i * 3 + 1] * K[1 * 3 + j]
                     + P[i * 3 + 2] * K[2 * 3 + j];
    // feat_hw = [128/4, 384/4] = [32, 96]; wh = flip = [96, 32]
    const float s0 = 2.0f / 95.0f;   // x comp: /(96-1)*2
    const float s1 = 2.0f / 31.0f;   // y comp: /(32-1)*2
    float pt0 = post_trans[c * 3 + 0];
    float pt1 = post_trans[c * 3 + 1];
    o[16] = s0 * PK[0][0];
    o[17] = s0 * PK[0][1];
    o[18] = s0 * (PK[0][2] + pt0) - 1.0f;
    o[19] = s1 * PK[1][0];
    o[20] = s1 * PK[1][1];
    o[21] = s1 * (PK[1][2] + pt1) - 1.0f;
}

// One thread per output point. blockIdx.x encodes ((bn*8+z)*256+x),
// threadIdx.x = y (contiguous in the output) -> coalesced float2 stores.
__global__ __launch_bounds__(256) void splat_kernel(const float* __restrict__ vox,
                                                    float2* __restrict__ out) {
    int bid = blockIdx.x;
    int y   = threadIdx.x;
    int x   = bid & 255;
    int z   = (bid >> 8) & 7;
    int bn  = bid >> 11;

    const float* cam = &g_cam[bn * 24];

    // voxels[z][y][x][c]: xs depends only on x, ys only on y, zs only on z.
    float vx = __ldg(&vox[x * 3 + 0]);             // voxels[0][0][x][0]
    float vy = __ldg(&vox[y * 768 + 1]);           // voxels[0][y][0][1]
    float vz = __ldg(&vox[z * 196608 + 2]);        // voxels[z][0][0][2]

    // p = R * v + t  (vx, vz uniform per block -> precompute base, fma in vy)
    float bx = cam[0] * vx + cam[2] * vz + cam[9];
    float by = cam[3] * vx + cam[5] * vz + cam[10];
    float bz = cam[6] * vx + cam[8] * vz + cam[11];
    float px = fmaf(cam[1], vy, bx);
    float py = fmaf(cam[4], vy, by);
    float pz = fmaf(cam[7], vy, bz);

    bool neg = pz < 0.0f;
    float sx = neg ? 9999.0f : px;
    float sy = neg ? 9999.0f : py;
    float inv = 1.0f / pz;
    sx *= inv;
    sy *= inv;

    float r  = sqrtf(sx * sx + sy * sy);
    float t  = atanf(r);                 // atan2(r, 1) with r >= 0
    float t2 = t * t;
    float poly = fmaf(t2, fmaf(t2, fmaf(t2, fmaf(t2, cam[15], cam[14]), cam[13]), cam[12]), 1.0f);
    float radial = t * poly / (r + 1e-6f);
    sx *= radial;
    sy *= radial;

    float o0 = fmaf(cam[16], sx, fmaf(cam[17], sy, cam[18]));
    float o1 = fmaf(cam[19], sx, fmaf(cam[20], sy, cam[21]));

    out[bid * 256 + y] = make_float2(o0, o1);
}

extern "C" void kernel_launch(void* const* d_in, const int* in_sizes, int n_in,
                              void* d_out, int out_size) {
    const float* voxels     = (const float*)d_in[0];
    const float* rots       = (const float*)d_in[1];
    const float* trans      = (const float*)d_in[2];
    const float* intrins    = (const float*)d_in[3];
    const float* distorts   = (const float*)d_in[4];
    const float* post_rots  = (const float*)d_in[5];
    const float* post_trans = (const float*)d_in[6];

    setup_kernel<<<1, 32>>>(rots, trans, intrins, distorts, post_rots, post_trans);
    splat_kernel<<<NCAM * 8 * 256, 256>>>(voxels, (float2*)d_out);
}

// round 5
// speedup vs baseline: 1.4338x; 1.4338x over previous
#include <cuda_runtime.h>

// Per-camera folded constants, computed by a tiny setup kernel each launch.
// Layout per camera (stride 24 floats):
//  [0..8]  R row-major, [9..11] t, [12..15] k1,k2,k3,k4,
//  [16..21] A0x,A0y,A0c,A1x,A1y,A1c  (post_rots@intrins rows 0/1 with
//           post_trans and the /(wh-1)*2-1 normalization folded in)
#define NCAM 24
__device__ float g_cam[NCAM * 24];

__global__ void setup_kernel(const float* __restrict__ rots,
                             const float* __restrict__ trans,
                             const float* __restrict__ intrins,
                             const float* __restrict__ distorts,
                             const float* __restrict__ post_rots,
                             const float* __restrict__ post_trans) {
    int c = threadIdx.x;
    if (c >= NCAM) return;
    float* o = &g_cam[c * 24];
    const float* R = rots + c * 9;
#pragma unroll
    for (int i = 0; i < 9; i++) o[i] = R[i];
    o[9]  = trans[c * 3 + 0];
    o[10] = trans[c * 3 + 1];
    o[11] = trans[c * 3 + 2];
    const float* d = distorts + c * 8;
    o[12] = d[0]; o[13] = d[1]; o[14] = d[4]; o[15] = d[5];
    const float* K = intrins + c * 9;
    const float* P = post_rots + c * 9;
    float PK[2][3];
#pragma unroll
    for (int i = 0; i < 2; i++)
#pragma unroll
        for (int j = 0; j < 3; j++)
            PK[i][j] = P[i * 3 + 0] * K[0 * 3 + j]
                     + P[i * 3 + 1] * K[1 * 3 + j]
                     + P[i * 3 + 2] * K[2 * 3 + j];
    // feat_hw = [128/4, 384/4] = [32, 96]; wh = flip = [96, 32]
    const float s0 = 2.0f / 95.0f;   // x comp: /(96-1)*2
    const float s1 = 2.0f / 31.0f;   // y comp: /(32-1)*2
    float pt0 = post_trans[c * 3 + 0];
    float pt1 = post_trans[c * 3 + 1];
    o[16] = s0 * PK[0][0];
    o[17] = s0 * PK[0][1];
    o[18] = s0 * (PK[0][2] + pt0) - 1.0f;
    o[19] = s1 * PK[1][0];
    o[20] = s1 * PK[1][1];
    o[21] = s1 * (PK[1][2] + pt1) - 1.0f;
}

// 4 output points per thread: cam constants, vx, vz, and the base rotation
// are loaded/computed ONCE per thread; only vy varies across the 4 points.
// Block = 128 threads covering 2 x-columns; thread (xi, ytid) handles
// y = ytid + 64*i, i in 0..3 -> each warp stores a contiguous 256B burst.
__global__ __launch_bounds__(128) void splat_kernel(const float* __restrict__ vox,
                                                    float2* __restrict__ out) {
    int bid  = blockIdx.x;
    int tid  = threadIdx.x;
    int xi   = tid >> 6;          // 0..1
    int ytid = tid & 63;          // 0..63
    int xp   = bid & 127;         // x pair
    int z    = (bid >> 7) & 7;
    int bn   = bid >> 10;
    int x    = xp * 2 + xi;

    const float* cam = &g_cam[bn * 24];
    // hoist all camera constants into registers (block-uniform LDGs)
    float r0 = cam[0], r1 = cam[1], r2 = cam[2];
    float r3 = cam[3], r4 = cam[4], r5 = cam[5];
    float r6 = cam[6], r7 = cam[7], r8 = cam[8];
    float t0 = cam[9], t1 = cam[10], t2 = cam[11];
    float k1 = cam[12], k2 = cam[13], k3 = cam[14], k4 = cam[15];
    float a0x = cam[16], a0y = cam[17], a0c = cam[18];
    float a1x = cam[19], a1y = cam[20], a1c = cam[21];

    // voxels[z][y][x][c]: xs depends only on x, ys only on y, zs only on z.
    float vx = __ldg(&vox[x * 3 + 0]);
    float vz = __ldg(&vox[z * 196608 + 2]);

    // per-thread-constant part of R*v + t
    float bx = fmaf(r0, vx, fmaf(r2, vz, t0));
    float by = fmaf(r3, vx, fmaf(r5, vz, t1));
    float bz = fmaf(r6, vx, fmaf(r8, vz, t2));

    float2* obase = out + (size_t)(((bn * 8 + z) * 256 + x)) * 256 + ytid;

#pragma unroll
    for (int i = 0; i < 4; i++) {
        int y = ytid + 64 * i;
        float vy = __ldg(&vox[y * 768 + 1]);

        float px = fmaf(r1, vy, bx);
        float py = fmaf(r4, vy, by);
        float pz = fmaf(r7, vy, bz);

        bool neg = pz < 0.0f;
        float sx = neg ? 9999.0f : px;
        float sy = neg ? 9999.0f : py;
        float inv = __fdividef(1.0f, pz);
        sx *= inv;
        sy *= inv;

        float r  = sqrtf(fmaf(sx, sx, sy * sy));
        float t  = atanf(r);                 // atan2(r, 1), r >= 0
        float t2v = t * t;
        float poly = fmaf(t2v, fmaf(t2v, fmaf(t2v, fmaf(t2v, k4, k3), k2), k1), 1.0f);
        float radial = t * poly * __fdividef(1.0f, r + 1e-6f);
        sx *= radial;
        sy *= radial;

        float o0 = fmaf(a0x, sx, fmaf(a0y, sy, a0c));
        float o1 = fmaf(a1x, sx, fmaf(a1y, sy, a1c));

        obase[64 * i] = make_float2(o0, o1);
    }
}

extern "C" void kernel_launch(void* const* d_in, const int* in_sizes, int n_in,
                              void* d_out, int out_size) {
    const float* voxels     = (const float*)d_in[0];
    const float* rots       = (const float*)d_in[1];
    const float* trans      = (const float*)d_in[2];
    const float* intrins    = (const float*)d_in[3];
    const float* distorts   = (const float*)d_in[4];
    const float* post_rots  = (const float*)d_in[5];
    const float* post_trans = (const float*)d_in[6];

    setup_kernel<<<1, 32>>>(rots, trans, intrins, distorts, post_rots, post_trans);
    splat_kernel<<<NCAM * 8 * 128, 128>>>(voxels, (float2*)d_out);
}

// round 6
// speedup vs baseline: 1.5801x; 1.1020x over previous
#include <cuda_runtime.h>

// Per-camera folded constants as 6 float4s, computed by a setup kernel.
//  f0 = (R00, R01, R02, t0)
//  f1 = (R10, R11, R12, t1)
//  f2 = (R20, R21, R22, t2)
//  f3 = (k1, k2, k3, k4)
//  f4 = (A0x, A0y, A0c, A1x)
//  f5 = (A1y, A1c, 0, 0)
// A rows = post_rots@intrins rows 0/1 with post_trans and the
// /(wh-1)*2-1 normalization folded in.
#define NCAM 24
__device__ float4 g_cam4[NCAM * 6];

__global__ void setup_kernel(const float* __restrict__ rots,
                             const float* __restrict__ trans,
                             const float* __restrict__ intrins,
                             const float* __restrict__ distorts,
                             const float* __restrict__ post_rots,
                             const float* __restrict__ post_trans) {
    int c = threadIdx.x;
    if (c >= NCAM) return;
    const float* R = rots + c * 9;
    const float* T = trans + c * 3;
    const float* d = distorts + c * 8;
    const float* K = intrins + c * 9;
    const float* P = post_rots + c * 9;

    float PK[2][3];
#pragma unroll
    for (int i = 0; i < 2; i++)
#pragma unroll
        for (int j = 0; j < 3; j++)
            PK[i][j] = P[i * 3 + 0] * K[0 * 3 + j]
                     + P[i * 3 + 1] * K[1 * 3 + j]
                     + P[i * 3 + 2] * K[2 * 3 + j];
    // feat_hw = [32, 96]; wh = flip = [96, 32]
    const float s0 = 2.0f / 95.0f;
    const float s1 = 2.0f / 31.0f;
    float a0x = s0 * PK[0][0];
    float a0y = s0 * PK[0][1];
    float a0c = s0 * (PK[0][2] + post_trans[c * 3 + 0]) - 1.0f;
    float a1x = s1 * PK[1][0];
    float a1y = s1 * PK[1][1];
    float a1c = s1 * (PK[1][2] + post_trans[c * 3 + 1]) - 1.0f;

    float4* o = &g_cam4[c * 6];
    o[0] = make_float4(R[0], R[1], R[2], T[0]);
    o[1] = make_float4(R[3], R[4], R[5], T[1]);
    o[2] = make_float4(R[6], R[7], R[8], T[2]);
    o[3] = make_float4(d[0], d[1], d[4], d[5]);
    o[4] = make_float4(a0x, a0y, a0c, a1x);
    o[5] = make_float4(a1y, a1c, 0.0f, 0.0f);
}

// 256-thread blocks cover (camera bn, z, 4 x-columns); each thread does 4 y
// points. vy (the only per-lane strided gather) is staged once per block in
// shared memory; the hot loop reads it via conflict-free LDS. Camera
// constants are 6 uniform LDG.128s. atanf replaced by a 5-term odd minimax
// with pi/2 - atan(1/r) reduction (reuses the 1/(r+1e-6) reciprocal).
__global__ __launch_bounds__(256) void splat_kernel(const float* __restrict__ vox,
                                                    float2* __restrict__ out) {
    __shared__ float s_vy[256];
    int tid = threadIdx.x;
    s_vy[tid] = __ldg(&vox[tid * 768 + 1]);   // voxels[0][y][0][1]

    int bid  = blockIdx.x;
    int xq   = bid & 63;
    int z    = (bid >> 6) & 7;
    int bn   = bid >> 9;
    int xi   = tid >> 6;          // 0..3
    int ytid = tid & 63;
    int x    = xq * 4 + xi;

    const float4* cam = &g_cam4[bn * 6];
    float4 f0 = cam[0], f1 = cam[1], f2 = cam[2];
    float4 f3 = cam[3], f4 = cam[4], f5 = cam[5];

    float vx = __ldg(&vox[x * 3 + 0]);         // voxels[0][0][x][0]
    float vz = __ldg(&vox[z * 196608 + 2]);    // voxels[z][0][0][2]

    // per-thread-constant part of R*v + t
    float bx = fmaf(f0.x, vx, fmaf(f0.z, vz, f0.w));
    float by = fmaf(f1.x, vx, fmaf(f1.z, vz, f1.w));
    float bz = fmaf(f2.x, vx, fmaf(f2.z, vz, f2.w));

    __syncthreads();

    float2* obase = out + (size_t)((bn * 8 + z) * 256 + x) * 256 + ytid;

#pragma unroll
    for (int i = 0; i < 4; i++) {
        float vy = s_vy[ytid + 64 * i];

        float px = fmaf(f0.y, vy, bx);
        float py = fmaf(f1.y, vy, by);
        float pz = fmaf(f2.y, vy, bz);

        bool neg = pz < 0.0f;
        float sx = neg ? 9999.0f : px;
        float sy = neg ? 9999.0f : py;
        float inv = __fdividef(1.0f, pz);
        sx *= inv;
        sy *= inv;

        float s2  = fmaf(sx, sx, sy * sy);
        float r   = sqrtf(s2);
        float rin = __fdividef(1.0f, r + 1e-6f);

        // t = atan(r), r >= 0: minimax on [0,1], pi/2 - atan(1/r) for r > 1
        bool  big = r > 1.0f;
        float u   = big ? rin : r;      // for r>1, 1/(r+1e-6) ~ 1/r (rel 1e-6)
        float u2  = u * u;
        float p = fmaf(u2, fmaf(u2, fmaf(u2, fmaf(u2, 0.0208351f, -0.0851330f),
                                          0.1801410f), -0.3302995f), 0.9998660f);
        float t = u * p;
        t = big ? 1.5707963f - t : t;

        float t2v  = t * t;
        float polyk = fmaf(t2v, fmaf(t2v, fmaf(t2v, fmaf(t2v, f3.w, f3.z), f3.y), f3.x), 1.0f);
        float radial = t * polyk * rin;
        sx *= radial;
        sy *= radial;

        float o0 = fmaf(f4.x, sx, fmaf(f4.y, sy, f4.z));
        float o1 = fmaf(f4.w, sx, fmaf(f5.x, sy, f5.y));

        obase[64 * i] = make_float2(o0, o1);
    }
}

extern "C" void kernel_launch(void* const* d_in, const int* in_sizes, int n_in,
                              void* d_out, int out_size) {
    const float* voxels     = (const float*)d_in[0];
    const float* rots       = (const float*)d_in[1];
    const float* trans      = (const float*)d_in[2];
    const float* intrins    = (const float*)d_in[3];
    const float* distorts   = (const float*)d_in[4];
    const float* post_rots  = (const float*)d_in[5];
    const float* post_trans = (const float*)d_in[6];

    setup_kernel<<<1, 32>>>(rots, trans, intrins, distorts, post_rots, post_trans);
    splat_kernel<<<NCAM * 8 * 64, 256>>>(voxels, (float2*)d_out);
}

// round 7
// speedup vs baseline: 2.7163x; 1.7190x over previous
#include <cuda_runtime.h>

// Per-camera folded constants as 6 float4s, computed by a setup kernel.
//  f0 = (R00, R01, R02, t0)
//  f1 = (R10, R11, R12, t1)
//  f2 = (R20, R21, R22, t2)
//  f3 = (k1, k2, k3, k4)
//  f4 = (A0x, A0y, A0c, A1x)
//  f5 = (A1y, A1c, 0, 0)
#define NCAM 24
__device__ float4 g_cam4[NCAM * 6];

__global__ void setup_kernel(const float* __restrict__ rots,
                             const float* __restrict__ trans,
                             const float* __restrict__ intrins,
                             const float* __restrict__ distorts,
                             const float* __restrict__ post_rots,
                             const float* __restrict__ post_trans) {
    int c = threadIdx.x;
    if (c >= NCAM) return;
    const float* R = rots + c * 9;
    const float* T = trans + c * 3;
    const float* d = distorts + c * 8;
    const float* K = intrins + c * 9;
    const float* P = post_rots + c * 9;

    float PK[2][3];
#pragma unroll
    for (int i = 0; i < 2; i++)
#pragma unroll
        for (int j = 0; j < 3; j++)
            PK[i][j] = P[i * 3 + 0] * K[0 * 3 + j]
                     + P[i * 3 + 1] * K[1 * 3 + j]
                     + P[i * 3 + 2] * K[2 * 3 + j];
    const float s0 = 2.0f / 95.0f;
    const float s1 = 2.0f / 31.0f;
    float a0x = s0 * PK[0][0];
    float a0y = s0 * PK[0][1];
    float a0c = s0 * (PK[0][2] + post_trans[c * 3 + 0]) - 1.0f;
    float a1x = s1 * PK[1][0];
    float a1y = s1 * PK[1][1];
    float a1c = s1 * (PK[1][2] + post_trans[c * 3 + 1]) - 1.0f;

    float4* o = &g_cam4[c * 6];
    o[0] = make_float4(R[0], R[1], R[2], T[0]);
    o[1] = make_float4(R[3], R[4], R[5], T[1]);
    o[2] = make_float4(R[6], R[7], R[8], T[2]);
    o[3] = make_float4(d[0], d[1], d[4], d[5]);
    o[4] = make_float4(a0x, a0y, a0c, a1x);
    o[5] = make_float4(a1y, a1c, 0.0f, 0.0f);
}

// ---- packed f32x2 helpers (sm_103a) ----
typedef unsigned long long u64;
__device__ __forceinline__ u64 pk(float lo, float hi) {
    u64 r; asm("mov.b64 %0, {%1, %2};" : "=l"(r) : "f"(lo), "f"(hi)); return r;
}
__device__ __forceinline__ void upk(float& lo, float& hi, u64 v) {
    asm("mov.b64 {%0, %1}, %2;" : "=f"(lo), "=f"(hi) : "l"(v));
}
__device__ __forceinline__ u64 f2fma(u64 a, u64 b, u64 c) {
    u64 d; asm("fma.rn.f32x2 %0, %1, %2, %3;" : "=l"(d) : "l"(a), "l"(b), "l"(c)); return d;
}
__device__ __forceinline__ u64 f2mul(u64 a, u64 b) {
    u64 d; asm("mul.rn.f32x2 %0, %1, %2;" : "=l"(d) : "l"(a), "l"(b)); return d;
}
__device__ __forceinline__ u64 f2add(u64 a, u64 b) {
    u64 d; asm("add.rn.f32x2 %0, %1, %2;" : "=l"(d) : "l"(a), "l"(b)); return d;
}

// 256-thread blocks cover (bn, z, 4 x-columns). Each thread handles 4 y
// points as TWO adjacent-y pairs; each pair rides the two lanes of packed
// f32x2 registers for the whole pipeline (rotation, both Horner polys, all
// pair muls). Scalar islands: selects + MUFU (RCP/RSQ). The pair's results
// interleave into a single STG.128.
__global__ __launch_bounds__(256) void splat_kernel(const float* __restrict__ vox,
                                                    float4* __restrict__ out4) {
    __shared__ float s_vy[256];
    int tid = threadIdx.x;
    s_vy[tid] = __ldg(&vox[tid * 768 + 1]);   // voxels[0][y][0][1]

    int bid = blockIdx.x;
    int xq  = bid & 63;
    int z   = (bid >> 6) & 7;
    int bn  = bid >> 9;
    int xi  = tid >> 6;          // 0..3
    int u   = tid & 63;          // y-pair index: y in {2u, 2u+1, 128+2u, 128+2u+1}
    int x   = xq * 4 + xi;

    const float4* cam = &g_cam4[bn * 6];
    float4 f0 = cam[0], f1 = cam[1], f2 = cam[2];
    float4 f3 = cam[3], f4 = cam[4], f5 = cam[5];

    float vx = __ldg(&vox[x * 3 + 0]);
    float vz = __ldg(&vox[z * 196608 + 2]);

    // per-thread-constant part of R*v + t (both lanes identical)
    float bx = fmaf(f0.x, vx, fmaf(f0.z, vz, f0.w));
    float by = fmaf(f1.x, vx, fmaf(f1.z, vz, f1.w));
    float bz = fmaf(f2.x, vx, fmaf(f2.z, vz, f2.w));

    u64 c_r1 = pk(f0.y, f0.y), c_r4 = pk(f1.y, f1.y), c_r7 = pk(f2.y, f2.y);
    u64 c_bx = pk(bx, bx), c_by = pk(by, by), c_bz = pk(bz, bz);
    u64 c_k1 = pk(f3.x, f3.x), c_k2 = pk(f3.y, f3.y);
    u64 c_k3 = pk(f3.z, f3.z), c_k4 = pk(f3.w, f3.w);
    u64 c_a0x = pk(f4.x, f4.x), c_a0y = pk(f4.y, f4.y), c_a0c = pk(f4.z, f4.z);
    u64 c_a1x = pk(f4.w, f4.w), c_a1y = pk(f5.x, f5.x), c_a1c = pk(f5.y, f5.y);

    __syncthreads();

    const float2* s_vy2 = reinterpret_cast<const float2*>(s_vy);
    // out4 index: (((bn*8+z)*256 + x)*256 + 2u)/2
    float4* obase = out4 + (size_t)((bn * 8 + z) * 256 + x) * 128 + u;

#pragma unroll
    for (int p = 0; p < 2; p++) {
        float2 vy = s_vy2[p * 64 + u];
        u64 vy2 = pk(vy.x, vy.y);

        u64 px2 = f2fma(c_r1, vy2, c_bx);
        u64 py2 = f2fma(c_r4, vy2, c_by);
        u64 pz2 = f2fma(c_r7, vy2, c_bz);

        float pxA, pxB, pyA, pyB, pzA, pzB;
        upk(pxA, pxB, px2); upk(pyA, pyB, py2); upk(pzA, pzB, pz2);

        float sxA = pzA < 0.0f ? 9999.0f : pxA;
        float syA = pzA < 0.0f ? 9999.0f : pyA;
        float sxB = pzB < 0.0f ? 9999.0f : pxB;
        float syB = pzB < 0.0f ? 9999.0f : pyB;
        u64 inv2 = pk(__fdividef(1.0f, pzA), __fdividef(1.0f, pzB));

        u64 sx2 = f2mul(pk(sxA, sxB), inv2);
        u64 sy2 = f2mul(pk(syA, syB), inv2);

        u64 s2 = f2fma(sx2, sx2, f2mul(sy2, sy2));
        s2 = f2add(s2, pk(1e-12f, 1e-12f));
        float s2A, s2B; upk(s2A, s2B, s2);
        float rinA = rsqrtf(s2A);           // 1/r
        float rinB = rsqrtf(s2B);
        float rA = s2A * rinA;              // r
        float rB = s2B * rinB;

        // t = atan(r): minimax on [0,1], pi/2 - atan(1/r) for r > 1
        float uA = rA > 1.0f ? rinA : rA;
        float uB = rB > 1.0f ? rinB : rB;
        u64 uu  = pk(uA, uB);
        u64 usq = f2mul(uu, uu);
        u64 pp  = f2fma(usq, f2fma(usq, f2fma(usq, f2fma(usq,
                      pk(0.0208351f, 0.0208351f), pk(-0.0851330f, -0.0851330f)),
                      pk(0.1801410f, 0.1801410f)), pk(-0.3302995f, -0.3302995f)),
                      pk(0.9998660f, 0.9998660f));
        u64 tp = f2mul(uu, pp);
        float tA, tB; upk(tA, tB, tp);
        tA = rA > 1.0f ? 1.5707963f - tA : tA;
        tB = rB > 1.0f ? 1.5707963f - tB : tB;
        u64 tt  = pk(tA, tB);
        u64 tsq = f2mul(tt, tt);
        u64 pkk = f2fma(tsq, f2fma(tsq, f2fma(tsq, f2fma(tsq, c_k4, c_k3), c_k2), c_k1),
                        pk(1.0f, 1.0f));
        u64 rad = f2mul(f2mul(tt, pkk), pk(rinA, rinB));

        sx2 = f2mul(sx2, rad);
        sy2 = f2mul(sy2, rad);

        u64 o0 = f2fma(c_a0x, sx2, f2fma(c_a0y, sy2, c_a0c));
        u64 o1 = f2fma(c_a1x, sx2, f2fma(c_a1y, sy2, c_a1c));
        float o0A, o0B, o1A, o1B;
        upk(o0A, o0B, o0); upk(o1A, o1B, o1);

        obase[p * 64] = make_float4(o0A, o1A, o0B, o1B);
    }
}

extern "C" void kernel_launch(void* const* d_in, const int* in_sizes, int n_in,
                              void* d_out, int out_size) {
    const float* voxels     = (const float*)d_in[0];
    const float* rots       = (const float*)d_in[1];
    const float* trans      = (const float*)d_in[2];
    const float* intrins    = (const float*)d_in[3];
    const float* distorts   = (const float*)d_in[4];
    const float* post_rots  = (const float*)d_in[5];
    const float* post_trans = (const float*)d_in[6];

    setup_kernel<<<1, 32>>>(rots, trans, intrins, distorts, post_rots, post_trans);
    splat_kernel<<<NCAM * 8 * 64, 256>>>(voxels, (float4*)d_out);
}

// round 8
// speedup vs baseline: 3.4596x; 1.2737x over previous
#include <cuda_runtime.h>

// Per-camera folded constants as 6 float4s + compact coordinate arrays,
// computed by a setup kernel each launch.
//  f0 = (R00, R01, R02, t0)
//  f1 = (R10, R11, R12, t1)
//  f2 = (R20, R21, R22, t2)
//  f3 = (k1, k2, k3, k4)
//  f4 = (A0x, A0y, A0c, A1x)
//  f5 = (A1y, A1c, 0, 0)
#define NCAM 24
__device__ float4 g_cam4[NCAM * 6];
__device__ float  g_vx[256];
__device__ float  g_vy[256];   // read as float2 pairs in the hot kernel
__device__ float  g_vz[8];

__global__ void setup_kernel(const float* __restrict__ vox,
                             const float* __restrict__ rots,
                             const float* __restrict__ trans,
                             const float* __restrict__ intrins,
                             const float* __restrict__ distorts,
                             const float* __restrict__ post_rots,
                             const float* __restrict__ post_trans) {
    int c = threadIdx.x;
    // compact coordinate arrays (one strided gather, done ONCE per launch)
    g_vx[c] = vox[c * 3 + 0];        // voxels[0][0][x][0]
    g_vy[c] = vox[c * 768 + 1];      // voxels[0][y][0][1]
    if (c < 8) g_vz[c] = vox[c * 196608 + 2];  // voxels[z][0][0][2]

    if (c >= NCAM) return;
    const float* R = rots + c * 9;
    const float* T = trans + c * 3;
    const float* d = distorts + c * 8;
    const float* K = intrins + c * 9;
    const float* P = post_rots + c * 9;

    float PK[2][3];
#pragma unroll
    for (int i = 0; i < 2; i++)
#pragma unroll
        for (int j = 0; j < 3; j++)
            PK[i][j] = P[i * 3 + 0] * K[0 * 3 + j]
                     + P[i * 3 + 1] * K[1 * 3 + j]
                     + P[i * 3 + 2] * K[2 * 3 + j];
    const float s0 = 2.0f / 95.0f;
    const float s1 = 2.0f / 31.0f;
    float a0x = s0 * PK[0][0];
    float a0y = s0 * PK[0][1];
    float a0c = s0 * (PK[0][2] + post_trans[c * 3 + 0]) - 1.0f;
    float a1x = s1 * PK[1][0];
    float a1y = s1 * PK[1][1];
    float a1c = s1 * (PK[1][2] + post_trans[c * 3 + 1]) - 1.0f;

    float4* o = &g_cam4[c * 6];
    o[0] = make_float4(R[0], R[1], R[2], T[0]);
    o[1] = make_float4(R[3], R[4], R[5], T[1]);
    o[2] = make_float4(R[6], R[7], R[8], T[2]);
    o[3] = make_float4(d[0], d[1], d[4], d[5]);
    o[4] = make_float4(a0x, a0y, a0c, a1x);
    o[5] = make_float4(a1y, a1c, 0.0f, 0.0f);
}

// ---- packed f32x2 helpers (sm_103a) ----
typedef unsigned long long u64;
__device__ __forceinline__ u64 pk(float lo, float hi) {
    u64 r; asm("mov.b64 %0, {%1, %2};" : "=l"(r) : "f"(lo), "f"(hi)); return r;
}
__device__ __forceinline__ void upk(float& lo, float& hi, u64 v) {
    asm("mov.b64 {%0, %1}, %2;" : "=f"(lo), "=f"(hi) : "l"(v));
}
__device__ __forceinline__ u64 f2fma(u64 a, u64 b, u64 c) {
    u64 d; asm("fma.rn.f32x2 %0, %1, %2, %3;" : "=l"(d) : "l"(a), "l"(b), "l"(c)); return d;
}
__device__ __forceinline__ u64 f2mul(u64 a, u64 b) {
    u64 d; asm("mul.rn.f32x2 %0, %1, %2;" : "=l"(d) : "l"(a), "l"(b)); return d;
}
__device__ __forceinline__ u64 f2add(u64 a, u64 b) {
    u64 d; asm("add.rn.f32x2 %0, %1, %2;" : "=l"(d) : "l"(a), "l"(b)); return d;
}

// 256-thread blocks cover (bn, 2 z-slices, 4 x-columns); each thread does
// 8 points: 2 z x 2 y-pairs, each pair riding the two lanes of packed f32x2
// registers. Camera constants and vy pairs are loaded once per thread and
// reused across both z. All coordinate loads hit the compact g_v* arrays
// (contiguous, L1-resident). Pair results interleave into STG.128.
__global__ __launch_bounds__(256) void splat_kernel(float4* __restrict__ out4) {
    int bid = blockIdx.x;
    int xq  = bid & 63;
    int zp  = (bid >> 6) & 3;
    int bn  = bid >> 8;
    int tid = threadIdx.x;
    int xi  = tid >> 6;          // 0..3
    int u   = tid & 63;          // y-pair index
    int x   = xq * 4 + xi;
    int z0  = zp * 2;

    const float4* cam = &g_cam4[bn * 6];
    float4 f0 = cam[0], f1 = cam[1], f2 = cam[2];
    float4 f3 = cam[3], f4 = cam[4], f5 = cam[5];

    float vx  = g_vx[x];
    float vz0 = g_vz[z0];
    float vz1 = g_vz[z0 + 1];

    const float2* vy2p = reinterpret_cast<const float2*>(g_vy);
    float2 vyA = vy2p[u];        // y = 2u, 2u+1
    float2 vyB = vy2p[64 + u];   // y = 128+2u, 128+2u+1
    u64 vyP[2] = { pk(vyA.x, vyA.y), pk(vyB.x, vyB.y) };

    u64 c_r1 = pk(f0.y, f0.y), c_r4 = pk(f1.y, f1.y), c_r7 = pk(f2.y, f2.y);
    u64 c_k1 = pk(f3.x, f3.x), c_k2 = pk(f3.y, f3.y);
    u64 c_k3 = pk(f3.z, f3.z), c_k4 = pk(f3.w, f3.w);
    u64 c_a0x = pk(f4.x, f4.x), c_a0y = pk(f4.y, f4.y), c_a0c = pk(f4.z, f4.z);
    u64 c_a1x = pk(f4.w, f4.w), c_a1y = pk(f5.x, f5.x), c_a1c = pk(f5.y, f5.y);

#pragma unroll
    for (int zi = 0; zi < 2; zi++) {
        float vz = zi ? vz1 : vz0;
        int   z  = z0 + zi;

        float bx = fmaf(f0.x, vx, fmaf(f0.z, vz, f0.w));
        float by = fmaf(f1.x, vx, fmaf(f1.z, vz, f1.w));
        float bz = fmaf(f2.x, vx, fmaf(f2.z, vz, f2.w));
        u64 c_bx = pk(bx, bx), c_by = pk(by, by), c_bz = pk(bz, bz);

        float4* obase = out4 + (size_t)((bn * 8 + z) * 256 + x) * 128 + u;

#pragma unroll
        for (int p = 0; p < 2; p++) {
            u64 vy2 = vyP[p];

            u64 px2 = f2fma(c_r1, vy2, c_bx);
            u64 py2 = f2fma(c_r4, vy2, c_by);
            u64 pz2 = f2fma(c_r7, vy2, c_bz);

            float pxA, pxB, pyA, pyB, pzA, pzB;
            upk(pxA, pxB, px2); upk(pyA, pyB, py2); upk(pzA, pzB, pz2);

            float sxA = pzA < 0.0f ? 9999.0f : pxA;
            float syA = pzA < 0.0f ? 9999.0f : pyA;
            float sxB = pzB < 0.0f ? 9999.0f : pxB;
            float syB = pzB < 0.0f ? 9999.0f : pyB;
            u64 inv2 = pk(__fdividef(1.0f, pzA), __fdividef(1.0f, pzB));

            u64 sx2 = f2mul(pk(sxA, sxB), inv2);
            u64 sy2 = f2mul(pk(syA, syB), inv2);

            u64 s2 = f2fma(sx2, sx2, f2mul(sy2, sy2));
            s2 = f2add(s2, pk(1e-12f, 1e-12f));
            float s2A, s2B; upk(s2A, s2B, s2);
            float rinA = rsqrtf(s2A);           // 1/r
            float rinB = rsqrtf(s2B);
            float rA = s2A * rinA;              // r
            float rB = s2B * rinB;

            // t = atan(r): minimax on [0,1], pi/2 - atan(1/r) for r > 1
            float uA = rA > 1.0f ? rinA : rA;
            float uB = rB > 1.0f ? rinB : rB;
            u64 uu  = pk(uA, uB);
            u64 usq = f2mul(uu, uu);
            u64 pp  = f2fma(usq, f2fma(usq, f2fma(usq, f2fma(usq,
                          pk(0.0208351f, 0.0208351f), pk(-0.0851330f, -0.0851330f)),
                          pk(0.1801410f, 0.1801410f)), pk(-0.3302995f, -0.3302995f)),
                          pk(0.9998660f, 0.9998660f));
            u64 tp = f2mul(uu, pp);
            float tA, tB; upk(tA, tB, tp);
            tA = rA > 1.0f ? 1.5707963f - tA : tA;
            tB = rB > 1.0f ? 1.5707963f - tB : tB;
            u64 tt  = pk(tA, tB);
            u64 tsq = f2mul(tt, tt);
            u64 pkk = f2fma(tsq, f2fma(tsq, f2fma(tsq, f2fma(tsq, c_k4, c_k3), c_k2), c_k1),
                            pk(1.0f, 1.0f));
            u64 rad = f2mul(f2mul(tt, pkk), pk(rinA, rinB));

            sx2 = f2mul(sx2, rad);
            sy2 = f2mul(sy2, rad);

            u64 o0 = f2fma(c_a0x, sx2, f2fma(c_a0y, sy2, c_a0c));
            u64 o1 = f2fma(c_a1x, sx2, f2fma(c_a1y, sy2, c_a1c));
            float o0A, o0B, o1A, o1B;
            upk(o0A, o0B, o0); upk(o1A, o1B, o1);

            obase[p * 64] = make_float4(o0A, o1A, o0B, o1B);
        }
    }
}

extern "C" void kernel_launch(void* const* d_in, const int* in_sizes, int n_in,
                              void* d_out, int out_size) {
    const float* voxels     = (const float*)d_in[0];
    const float* rots       = (const float*)d_in[1];
    const float* trans      = (const float*)d_in[2];
    const float* intrins    = (const float*)d_in[3];
    const float* distorts   = (const float*)d_in[4];
    const float* post_rots  = (const float*)d_in[5];
    const float* post_trans = (const float*)d_in[6];

    setup_kernel<<<1, 256>>>(voxels, rots, trans, intrins, distorts,
                             post_rots, post_trans);
    splat_kernel<<<NCAM * 4 * 64, 256>>>((float4*)d_out);
}

// round 11
// speedup vs baseline: 3.4923x; 1.0094x over previous
#include <cuda_runtime.h>

// Per-camera folded constants as 6 float4s + compact coordinate arrays,
// computed by a setup kernel each launch.
//  f0 = (R00, R01, R02, t0)
//  f1 = (R10, R11, R12, t1)
//  f2 = (R20, R21, R22, t2)
//  f3 = (k1, k2, k3, k4)
//  f4 = (A0x, A0y, A0c, A1x)
//  f5 = (A1y, A1c, 0, 0)
#define NCAM 24
__device__ float4 g_cam4[NCAM * 6];
__device__ float  g_vx[256];
__device__ float  g_vy[256];   // read as float2 pairs in the hot kernel
__device__ float  g_vz[8];

__global__ void setup_kernel(const float* __restrict__ vox,
                             const float* __restrict__ rots,
                             const float* __restrict__ trans,
                             const float* __restrict__ intrins,
                             const float* __restrict__ distorts,
                             const float* __restrict__ post_rots,
                             const float* __restrict__ post_trans) {
    int c = threadIdx.x;
    // compact coordinate arrays (one strided gather, done ONCE per launch)
    g_vx[c] = vox[c * 3 + 0];        // voxels[0][0][x][0]
    g_vy[c] = vox[c * 768 + 1];      // voxels[0][y][0][1]
    if (c < 8) g_vz[c] = vox[c * 196608 + 2];  // voxels[z][0][0][2]

    if (c >= NCAM) return;
    const float* R = rots + c * 9;
    const float* T = trans + c * 3;
    const float* d = distorts + c * 8;
    const float* K = intrins + c * 9;
    const float* P = post_rots + c * 9;

    float PK[2][3];
#pragma unroll
    for (int i = 0; i < 2; i++)
#pragma unroll
        for (int j = 0; j < 3; j++)
            PK[i][j] = P[i * 3 + 0] * K[0 * 3 + j]
                     + P[i * 3 + 1] * K[1 * 3 + j]
                     + P[i * 3 + 2] * K[2 * 3 + j];
    const float s0 = 2.0f / 95.0f;
    const float s1 = 2.0f / 31.0f;
    float a0x = s0 * PK[0][0];
    float a0y = s0 * PK[0][1];
    float a0c = s0 * (PK[0][2] + post_trans[c * 3 + 0]) - 1.0f;
    float a1x = s1 * PK[1][0];
    float a1y = s1 * PK[1][1];
    float a1c = s1 * (PK[1][2] + post_trans[c * 3 + 1]) - 1.0f;

    float4* o = &g_cam4[c * 6];
    o[0] = make_float4(R[0], R[1], R[2], T[0]);
    o[1] = make_float4(R[3], R[4], R[5], T[1]);
    o[2] = make_float4(R[6], R[7], R[8], T[2]);
    o[3] = make_float4(d[0], d[1], d[4], d[5]);
    o[4] = make_float4(a0x, a0y, a0c, a1x);
    o[5] = make_float4(a1y, a1c, 0.0f, 0.0f);
}

// ---- packed f32x2 helpers (sm_103a) ----
typedef unsigned long long u64;
__device__ __forceinline__ u64 pk(float lo, float hi) {
    u64 r; asm("mov.b64 %0, {%1, %2};" : "=l"(r) : "f"(lo), "f"(hi)); return r;
}
__device__ __forceinline__ void upk(float& lo, float& hi, u64 v) {
    asm("mov.b64 {%0, %1}, %2;" : "=f"(lo), "=f"(hi) : "l"(v));
}
__device__ __forceinline__ u64 f2fma(u64 a, u64 b, u64 c) {
    u64 d; asm("fma.rn.f32x2 %0, %1, %2, %3;" : "=l"(d) : "l"(a), "l"(b), "l"(c)); return d;
}
__device__ __forceinline__ u64 f2mul(u64 a, u64 b) {
    u64 d; asm("mul.rn.f32x2 %0, %1, %2;" : "=l"(d) : "l"(a), "l"(b)); return d;
}

// 256-thread blocks cover (bn, 2 z-slices, 4 x-columns); each thread does
// 8 points: 2 z x 2 y-pairs, each pair riding the two lanes of packed f32x2
// registers. fminf-based atan range reduction keeps the polynomial off the
// FSETP->FSEL latency path. 32-bit output indexing. launch_bounds(256,6)
// clamps regs to lift occupancy to 6 blocks/SM.
__global__ __launch_bounds__(256, 6) void splat_kernel(float4* __restrict__ out4) {
    int bid = blockIdx.x;
    int xq  = bid & 63;
    int zp  = (bid >> 6) & 3;
    int bn  = bid >> 8;
    int tid = threadIdx.x;
    int xi  = tid >> 6;          // 0..3
    int u   = tid & 63;          // y-pair index
    int x   = xq * 4 + xi;
    int z0  = zp * 2;

    const float4* cam = &g_cam4[bn * 6];
    float4 f0 = cam[0], f1 = cam[1], f2 = cam[2];
    float4 f3 = cam[3], f4 = cam[4], f5 = cam[5];

    float vx  = g_vx[x];
    float vz0 = g_vz[z0];
    float vz1 = g_vz[z0 + 1];

    const float2* vy2p = reinterpret_cast<const float2*>(g_vy);
    float2 vyA = vy2p[u];        // y = 2u, 2u+1
    float2 vyB = vy2p[64 + u];   // y = 128+2u, 128+2u+1
    u64 vyP[2] = { pk(vyA.x, vyA.y), pk(vyB.x, vyB.y) };

    u64 c_r1 = pk(f0.y, f0.y), c_r4 = pk(f1.y, f1.y), c_r7 = pk(f2.y, f2.y);
    u64 c_k1 = pk(f3.x, f3.x), c_k2 = pk(f3.y, f3.y);
    u64 c_k3 = pk(f3.z, f3.z), c_k4 = pk(f3.w, f3.w);
    u64 c_a0x = pk(f4.x, f4.x), c_a0y = pk(f4.y, f4.y), c_a0c = pk(f4.z, f4.z);
    u64 c_a1x = pk(f4.w, f4.w), c_a1y = pk(f5.x, f5.x), c_a1c = pk(f5.y, f5.y);
    const u64 c_eps = pk(1e-12f, 1e-12f);
    const u64 c_one = pk(1.0f, 1.0f);

#pragma unroll
    for (int zi = 0; zi < 2; zi++) {
        float vz = zi ? vz1 : vz0;
        int   z  = z0 + zi;

        float bx = fmaf(f0.x, vx, fmaf(f0.z, vz, f0.w));
        float by = fmaf(f1.x, vx, fmaf(f1.z, vz, f1.w));
        float bz = fmaf(f2.x, vx, fmaf(f2.z, vz, f2.w));
        u64 c_bx = pk(bx, bx), c_by = pk(by, by), c_bz = pk(bz, bz);

        // 32-bit float4 index (max 6.29M, fits easily)
        unsigned obase = (unsigned)(((bn * 8 + z) * 256 + x) * 128 + u);

#pragma unroll
        for (int p = 0; p < 2; p++) {
            u64 vy2 = vyP[p];

            u64 px2 = f2fma(c_r1, vy2, c_bx);
            u64 py2 = f2fma(c_r4, vy2, c_by);
            u64 pz2 = f2fma(c_r7, vy2, c_bz);

            float pxA, pxB, pyA, pyB, pzA, pzB;
            upk(pxA, pxB, px2); upk(pyA, pyB, py2); upk(pzA, pzB, pz2);

            float sxA = pzA < 0.0f ? 9999.0f : pxA;
            float syA = pzA < 0.0f ? 9999.0f : pyA;
            float sxB = pzB < 0.0f ? 9999.0f : pxB;
            float syB = pzB < 0.0f ? 9999.0f : pyB;
            u64 inv2 = pk(__fdividef(1.0f, pzA), __fdividef(1.0f, pzB));

            u64 sx2 = f2mul(pk(sxA, sxB), inv2);
            u64 sy2 = f2mul(pk(syA, syB), inv2);

            // s2 = sx^2 + sy^2 + eps  (eps folded into the inner fma)
            u64 s2 = f2fma(sx2, sx2, f2fma(sy2, sy2, c_eps));
            float s2A, s2B; upk(s2A, s2B, s2);
            float rinA = rsqrtf(s2A);           // 1/r
            float rinB = rsqrtf(s2B);
            u64 rin2 = pk(rinA, rinB);
            u64 r2v  = f2mul(s2, rin2);         // r = s2 * (1/r)
            float rA, rB; upk(rA, rB, r2v);

            // t = atan(r): poly on u = min(r, 1/r); flip by pi/2 - t if r>1.
            // fminf keeps the poly off the predicate latency path.
            float uA = fminf(rA, rinA);
            float uB = fminf(rB, rinB);
            u64 uu  = pk(uA, uB);
            u64 usq = f2mul(uu, uu);
            u64 pp  = f2fma(usq, f2fma(usq, f2fma(usq, f2fma(usq,
                          pk(0.0208351f, 0.0208351f), pk(-0.0851330f, -0.0851330f)),
                          pk(0.1801410f, 0.1801410f)), pk(-0.3302995f, -0.3302995f)),
                          pk(0.9998660f, 0.9998660f));
            u64 tp = f2mul(uu, pp);
            float tA, tB; upk(tA, tB, tp);
            tA = rA > 1.0f ? 1.5707963f - tA : tA;
            tB = rB > 1.0f ? 1.5707963f - tB : tB;
            u64 tt  = pk(tA, tB);
            u64 tsq = f2mul(tt, tt);
            u64 pkk = f2fma(tsq, f2fma(tsq, f2fma(tsq, f2fma(tsq, c_k4, c_k3), c_k2), c_k1),
                            c_one);
            u64 rad = f2mul(f2mul(tt, pkk), rin2);

            sx2 = f2mul(sx2, rad);
            sy2 = f2mul(sy2, rad);

            u64 o0 = f2fma(c_a0x, sx2, f2fma(c_a0y, sy2, c_a0c));
            u64 o1 = f2fma(c_a1x, sx2, f2fma(c_a1y, sy2, c_a1c));
            float o0A, o0B, o1A, o1B;
            upk(o0A, o0B, o0); upk(o1A, o1B, o1);

            out4[obase + p * 64] = make_float4(o0A, o1A, o0B, o1B);
        }
    }
}

extern "C" void kernel_launch(void* const* d_in, const int* in_sizes, int n_in,
                              void* d_out, int out_size) {
    const float* voxels     = (const float*)d_in[0];
    const float* rots       = (const float*)d_in[1];
    const float* trans      = (const float*)d_in[2];
    const float* intrins    = (const float*)d_in[3];
    const float* distorts   = (const float*)d_in[4];
    const float* post_rots  = (const float*)d_in[5];
    const float* post_trans = (const float*)d_in[6];

    setup_kernel<<<1, 256>>>(voxels, rots, trans, intrins, distorts,
                             post_rots, post_trans);
    splat_kernel<<<NCAM * 4 * 64, 256>>>((float4*)d_out);
}